// round 13
// baseline (speedup 1.0000x reference)
#include <cuda_runtime.h>
#include <cuda_fp16.h>
#include <cstdint>
#include <cstddef>

// Problem constants (fixed dataset: B=8 seqs, E=2048, T=24576, max_len=4096)
#define E_DIM 2048
#define T_MAX 24576
#define B_MAX 8
#define EPS_RMS 1e-6f

#define STAGES 3
#define BK 64
#define ST_H 72                          // 64 + 8 halves; 144B stride -> LDSM conflict-free
#define TILE_H (128 * ST_H)              // halves per (A or B) stage
#define STG_BYTES (2 * TILE_H * 2)       // A+B stage bytes (36864)
#define GEMM_SMEM (STAGES * STG_BYTES)   // 110592 bytes

// ---------------- scratch (device globals; allocation-free contract) -------
__device__ __align__(16) __half g_Xh[T_MAX * 2048];    // fp16 inputs
__device__ __align__(16) __half g_W1h[2048 * 2048];    // packed L1 weights [n][k]
__device__ __align__(16) __half g_W2h[4096 * 1024];    // packed L2 weights [n][k]
__device__ __align__(16) __half g_O1h[T_MAX * 1024];   // o1 per token (fp16)
__device__ __align__(16) __half g_C1h[T_MAX * 2048];   // L1 both taps (fp16)
__device__ __align__(16) __half g_C2h[T_MAX * 4096];   // L2 both taps (fp16)
__device__ float g_p0[B_MAX * 1024];   // W1_tap0 . x_prev(first token) per seq
__device__ float g_q0[B_MAX * 2048];   // W2_tap0 . o1_prev(first token) per seq

__device__ __forceinline__ uint32_t smem_u32(const void* p) {
    return (uint32_t)__cvta_generic_to_shared(p);
}

// ---------------- X -> fp16 ------------------------------------------------
__global__ void x_to_half(const float* __restrict__ X, int n8) {
    int idx = blockIdx.x * blockDim.x + threadIdx.x;
    if (idx >= n8) return;
    const float4* xp = (const float4*)(X) + idx * 2;
    float4 a = xp[0], b = xp[1];
    __half2 h0 = __floats2half2_rn(a.x, a.y);
    __half2 h1 = __floats2half2_rn(a.z, a.w);
    __half2 h2 = __floats2half2_rn(b.x, b.y);
    __half2 h3 = __floats2half2_rn(b.z, b.w);
    uint4 v = make_uint4(*(uint32_t*)&h0, *(uint32_t*)&h1,
                         *(uint32_t*)&h2, *(uint32_t*)&h3);
    *((uint4*)g_Xh + idx) = v;
}

// ---------------- weight packing to fp16, [n][k] layout --------------------
__global__ void pack_weights(const float* __restrict__ w1,
                             const float* __restrict__ w2) {
    const int total1 = 2048 * 2048;
    const int total2 = 4096 * 1024;
    for (int i = blockIdx.x * blockDim.x + threadIdx.x; i < total1 + total2;
         i += gridDim.x * blockDim.x) {
        if (i < total1) {
            int n = i >> 11, k = i & 2047;
            float v = (n < 1024) ? w1[n * 4096 + k * 2 + 1]
                                 : w1[(n - 1024) * 4096 + k * 2];
            g_W1h[i] = __float2half_rn(v);
        } else {
            int j = i - total1;
            int n = j >> 10, k = j & 1023;
            float v = (n < 2048) ? w2[n * 2048 + k * 2 + 1]
                                 : w2[(n - 2048) * 2048 + k * 2];
            g_W2h[j] = __float2half_rn(v);
        }
    }
}

// ---------------- per-sequence boundary vectors (warp per output) ----------
__global__ void init_vecs(const float* __restrict__ w1,
                          const float* __restrict__ w2,
                          const float* __restrict__ b1,
                          const float* __restrict__ lf1,
                          const float* __restrict__ lf2,
                          const int* __restrict__ lens,
                          const int* __restrict__ maxlen_p, int Bn) {
    int gw = (blockIdx.x * blockDim.x + threadIdx.x) >> 5;
    int lane = threadIdx.x & 31;
    int ml = maxlen_p ? *maxlen_p : 4096;
    int n_p0 = Bn * 1024;
    float s = 0.f;
    if (gw < n_p0) {
        int b = gw >> 10, o = gw & 1023;
        if (lens[b] == ml) {
            const float* wr = w1 + (size_t)o * 4096;
            const float* xr = lf1 + b * 2048;
            for (int i = lane; i < 2048; i += 32) s += wr[i * 2] * xr[i];
        }
#pragma unroll
        for (int off = 16; off; off >>= 1)
            s += __shfl_xor_sync(0xffffffffu, s, off);
        if (lane == 0) g_p0[gw] = s;
    } else if (gw < n_p0 + Bn * 2048) {
        int j = gw - n_p0;
        int b = j >> 11, o = j & 2047;
        bool full = (lens[b] == ml);
        const float* wr = w2 + (size_t)o * 2048;
        const float* vr = full ? (lf2 + b * 1024) : b1;
        for (int i = lane; i < 1024; i += 32) s += wr[i * 2] * vr[i];
#pragma unroll
        for (int off = 16; off; off >>= 1)
            s += __shfl_xor_sync(0xffffffffu, s, off);
        if (lane == 0) g_q0[j] = s;
    }
}

// ---------------- fp16 tensor-core GEMM: C[M,N] = A[M,K] @ Bt[N,K]^T -------
// 128x128x64 block tile, 256 threads = 2x4 warps (warp tile 64x32),
// mma.sync.m16n8k16, ldmatrix, 3-stage cp.async, fp16 C output.
// Two-buffer fragment pipeline: LDSM(kk+1) issued before MMA(kk).
__global__ __launch_bounds__(256, 2)
void gemm_f16(const __half* __restrict__ A, const __half* __restrict__ Bt,
              __half* __restrict__ C, int M, int N, int K) {
    extern __shared__ __half smem[];
    const uint32_t sb = smem_u32(smem);

    const int tid = threadIdx.x;
    const int warp = tid >> 5, lane = tid & 31;
    const int gid = lane >> 2, tid4 = lane & 3;
    const int wm = (warp >> 2) * 64;      // warp row offset in tile
    const int wn = (warp & 3) * 32;       // warp col offset in tile
    const int row0 = blockIdx.y * 128;
    const int col0 = blockIdx.x * 128;
    const int ktiles = K / BK;

    // per-lane ldmatrix byte offsets within a stage
    uint32_t aoff[4], boff[2];
#pragma unroll
    for (int mi = 0; mi < 4; mi++)
        aoff[mi] = ((wm + mi * 16 + (lane & 15)) * ST_H + (lane >> 4) * 8) * 2;
#pragma unroll
    for (int nj2 = 0; nj2 < 2; nj2++)
        boff[nj2] = ((wn + nj2 * 16 + ((lane >> 4) & 1) * 8 + (lane & 7)) * ST_H +
                     ((lane >> 3) & 1) * 8) * 2;

    float acc[4][4][4];
#pragma unroll
    for (int i = 0; i < 4; i++)
#pragma unroll
        for (int j = 0; j < 4; j++)
#pragma unroll
            for (int r = 0; r < 4; r++) acc[i][j][r] = 0.f;

    const __half* Abase = A + (size_t)row0 * K;
    const __half* Bbase = Bt + (size_t)col0 * K;

#define LOAD_STAGE(st, kt)                                                     \
    do {                                                                       \
        uint32_t ad = sb + (st) * STG_BYTES;                                   \
        uint32_t bd = ad + TILE_H * 2;                                         \
        _Pragma("unroll") for (int q = 0; q < 4; q++) {                        \
            int idx = tid + q * 256;                                           \
            int r = idx >> 3, c8 = (idx & 7) * 8;                              \
            asm volatile("cp.async.cg.shared.global [%0], [%1], 16;" ::        \
                             "r"(ad + (r * ST_H + c8) * 2),                    \
                             "l"(Abase + (size_t)r * K + (kt) * BK + c8));     \
        }                                                                      \
        _Pragma("unroll") for (int q = 0; q < 4; q++) {                        \
            int idx = tid + q * 256;                                           \
            int r = idx >> 3, c8 = (idx & 7) * 8;                              \
            asm volatile("cp.async.cg.shared.global [%0], [%1], 16;" ::        \
                             "r"(bd + (r * ST_H + c8) * 2),                    \
                             "l"(Bbase + (size_t)r * K + (kt) * BK + c8));     \
        }                                                                      \
    } while (0)

#define DO_LDSM(af, bf, kk)                                                    \
    do {                                                                       \
        _Pragma("unroll") for (int mi = 0; mi < 4; mi++)                       \
            asm volatile(                                                      \
                "ldmatrix.sync.aligned.m8n8.x4.shared.b16 {%0,%1,%2,%3}, [%4];"\
                : "=r"((af)[mi][0]), "=r"((af)[mi][1]), "=r"((af)[mi][2]),     \
                  "=r"((af)[mi][3])                                            \
                : "r"(as + aoff[mi] + (kk) * 32));                             \
        _Pragma("unroll") for (int nj2 = 0; nj2 < 2; nj2++)                    \
            asm volatile(                                                      \
                "ldmatrix.sync.aligned.m8n8.x4.shared.b16 {%0,%1,%2,%3}, [%4];"\
                : "=r"((bf)[nj2][0]), "=r"((bf)[nj2][1]), "=r"((bf)[nj2][2]),  \
                  "=r"((bf)[nj2][3])                                           \
                : "r"(bs + boff[nj2] + (kk) * 32));                            \
    } while (0)

#define DO_MMA(af, bf)                                                         \
    do {                                                                       \
        _Pragma("unroll") for (int mi = 0; mi < 4; mi++)                       \
            _Pragma("unroll") for (int nj = 0; nj < 4; nj++) {                 \
                const uint32_t b0 = (bf)[nj >> 1][(nj & 1) * 2];               \
                const uint32_t b1 = (bf)[nj >> 1][(nj & 1) * 2 + 1];           \
                asm volatile(                                                  \
                    "mma.sync.aligned.m16n8k16.row.col.f32.f16.f16.f32 "       \
                    "{%0,%1,%2,%3}, {%4,%5,%6,%7}, {%8,%9}, {%0,%1,%2,%3};"    \
                    : "+f"(acc[mi][nj][0]), "+f"(acc[mi][nj][1]),              \
                      "+f"(acc[mi][nj][2]), "+f"(acc[mi][nj][3])               \
                    : "r"((af)[mi][0]), "r"((af)[mi][1]), "r"((af)[mi][2]),    \
                      "r"((af)[mi][3]), "r"(b0), "r"(b1));                     \
            }                                                                  \
    } while (0)

    // prime pipeline: 2 stages
#pragma unroll
    for (int s = 0; s < STAGES - 1; s++) {
        if (s < ktiles) LOAD_STAGE(s, s);
        asm volatile("cp.async.commit_group;");
    }

    int st_cur = 0;                       // kt % 3, tracked incrementally
    int st_nxt = STAGES - 1;              // (kt + STAGES - 1) % 3
    for (int kt = 0; kt < ktiles; kt++) {
        asm volatile("cp.async.wait_group %0;" ::"n"(STAGES - 2));
        __syncthreads();

        uint32_t as = sb + st_cur * STG_BYTES;
        uint32_t bs = as + TILE_H * 2;
        if (++st_cur == STAGES) st_cur = 0;

        uint32_t af0[4][4], bf0[2][4], af1[4][4], bf1[2][4];
        DO_LDSM(af0, bf0, 0);
        DO_LDSM(af1, bf1, 1);
        DO_MMA(af0, bf0);

        if (kt + STAGES - 1 < ktiles) LOAD_STAGE(st_nxt, kt + STAGES - 1);
        asm volatile("cp.async.commit_group;");
        if (++st_nxt == STAGES) st_nxt = 0;

        DO_LDSM(af0, bf0, 2);
        DO_MMA(af1, bf1);
        DO_LDSM(af1, bf1, 3);
        DO_MMA(af0, bf0);
        DO_MMA(af1, bf1);
    }

    // epilogue (fp16 output)
#pragma unroll
    for (int mi = 0; mi < 4; mi++) {
        int r0 = row0 + wm + mi * 16 + gid;
#pragma unroll
        for (int nj = 0; nj < 4; nj++) {
            int c = col0 + wn + nj * 8 + tid4 * 2;
            __half2 h0 = __floats2half2_rn(acc[mi][nj][0], acc[mi][nj][1]);
            __half2 h1 = __floats2half2_rn(acc[mi][nj][2], acc[mi][nj][3]);
            *(__half2*)&C[(size_t)r0 * N + c] = h0;
            *(__half2*)&C[(size_t)(r0 + 8) * N + c] = h1;
        }
    }
#undef LOAD_STAGE
#undef DO_LDSM
#undef DO_MMA
}

// ---- combine 1: o1 = C1h[t-1,1024+o]|p0 + C1h[t,o] + b1 -> fp16 O1h -------
// One thread per 8 outputs: T*128 threads.
__global__ void combine1(const float* __restrict__ b1,
                         const int* __restrict__ start, int Bn, int T) {
    int idx = blockIdx.x * blockDim.x + threadIdx.x;
    if (idx >= T * 128) return;
    int t = idx >> 7;
    int o = (idx & 127) << 3;
    int b = 0;
#pragma unroll
    for (int i = 1; i < 8; i++)
        if (i < Bn && t >= start[i]) b = i;

    uint4 curh = *(const uint4*)&g_C1h[(size_t)t * 2048 + o];
    float pv[8];
    if (t > start[b]) {
        uint4 ph = *(const uint4*)&g_C1h[(size_t)(t - 1) * 2048 + 1024 + o];
        const __half2* p2 = (const __half2*)&ph;
#pragma unroll
        for (int i = 0; i < 4; i++) {
            float2 f = __half22float2(p2[i]);
            pv[i * 2] = f.x; pv[i * 2 + 1] = f.y;
        }
    } else {
        float4 p0a = *(const float4*)&g_p0[b * 1024 + o];
        float4 p0b = *(const float4*)&g_p0[b * 1024 + o + 4];
        pv[0] = p0a.x; pv[1] = p0a.y; pv[2] = p0a.z; pv[3] = p0a.w;
        pv[4] = p0b.x; pv[5] = p0b.y; pv[6] = p0b.z; pv[7] = p0b.w;
    }
    float4 bba = *(const float4*)&b1[o];
    float4 bbb = *(const float4*)&b1[o + 4];
    float bv[8] = {bba.x, bba.y, bba.z, bba.w, bbb.x, bbb.y, bbb.z, bbb.w};

    const __half2* c2 = (const __half2*)&curh;
    __half2 r[4];
#pragma unroll
    for (int i = 0; i < 4; i++) {
        float2 f = __half22float2(c2[i]);
        r[i] = __floats2half2_rn(f.x + pv[i * 2] + bv[i * 2],
                                 f.y + pv[i * 2 + 1] + bv[i * 2 + 1]);
    }
    *(uint4*)&g_O1h[(size_t)t * 1024 + o] = *(uint4*)r;
}

// ---------------- combine 2 + RMSNorm: one block per token -----------------
// Residual read from fp16 Xh (saves 100MB vs fp32 X).
__global__ __launch_bounds__(256)
void combine2_norm(const float* __restrict__ b2,
                   const float* __restrict__ gamma,
                   const int* __restrict__ start, int Bn,
                   float* __restrict__ out) {
    int t = blockIdx.x;
    int tid = threadIdx.x;
    int b = 0;
#pragma unroll
    for (int i = 1; i < 8; i++)
        if (i < Bn && t >= start[i]) b = i;
    bool first = (t == start[b]);
    int o = tid * 8;

    uint4 curh = *(const uint4*)&g_C2h[(size_t)t * 4096 + o];
    float pv[8];
    if (!first) {
        uint4 ph = *(const uint4*)&g_C2h[(size_t)(t - 1) * 4096 + 2048 + o];
        const __half2* p2 = (const __half2*)&ph;
#pragma unroll
        for (int i = 0; i < 4; i++) {
            float2 f = __half22float2(p2[i]);
            pv[i * 2] = f.x; pv[i * 2 + 1] = f.y;
        }
    } else {
        float4 qa = *(const float4*)&g_q0[b * 2048 + o];
        float4 qb = *(const float4*)&g_q0[b * 2048 + o + 4];
        pv[0] = qa.x; pv[1] = qa.y; pv[2] = qa.z; pv[3] = qa.w;
        pv[4] = qb.x; pv[5] = qb.y; pv[6] = qb.z; pv[7] = qb.w;
    }
    uint4 xh = *(const uint4*)&g_Xh[(size_t)t * 2048 + o];
    const __half2* x2 = (const __half2*)&xh;
    float xv[8];
#pragma unroll
    for (int i = 0; i < 4; i++) {
        float2 f = __half22float2(x2[i]);
        xv[i * 2] = f.x; xv[i * 2 + 1] = f.y;
    }
    float4 ba = *(const float4*)&b2[o];
    float4 bb = *(const float4*)&b2[o + 4];
    float bv[8] = {ba.x, ba.y, ba.z, ba.w, bb.x, bb.y, bb.z, bb.w};

    const __half2* c2 = (const __half2*)&curh;
    float vals[8];
    float sumsq = 0.f;
#pragma unroll
    for (int i = 0; i < 4; i++) {
        float2 f = __half22float2(c2[i]);
        float v0 = f.x + pv[i * 2] + xv[i * 2] + bv[i * 2];
        float v1 = f.y + pv[i * 2 + 1] + xv[i * 2 + 1] + bv[i * 2 + 1];
        vals[i * 2] = v0; vals[i * 2 + 1] = v1;
        sumsq += v0 * v0 + v1 * v1;
    }

#pragma unroll
    for (int off = 16; off; off >>= 1)
        sumsq += __shfl_xor_sync(0xffffffffu, sumsq, off);
    __shared__ float red[8];
    __shared__ float s_rs;
    if ((tid & 31) == 0) red[tid >> 5] = sumsq;
    __syncthreads();
    if (tid == 0) {
        float s = 0.f;
#pragma unroll
        for (int i = 0; i < 8; i++) s += red[i];
        s_rs = rsqrtf(s / (float)E_DIM + EPS_RMS);
    }
    __syncthreads();
    float r = s_rs;
    float4 ga = *(const float4*)&gamma[o];
    float4 gb = *(const float4*)&gamma[o + 4];
    float gv[8] = {ga.x, ga.y, ga.z, ga.w, gb.x, gb.y, gb.z, gb.w};
    float4 o0 = make_float4(vals[0] * r * gv[0], vals[1] * r * gv[1],
                            vals[2] * r * gv[2], vals[3] * r * gv[3]);
    float4 o1 = make_float4(vals[4] * r * gv[4], vals[5] * r * gv[5],
                            vals[6] * r * gv[6], vals[7] * r * gv[7]);
    *(float4*)&out[(size_t)t * 2048 + o] = o0;
    *(float4*)&out[(size_t)t * 2048 + o + 4] = o1;
}

// ---------------- cache outputs: lf1 = x[last] (exact fp32), lf2 = o1[last] -
__global__ void tails(const float* __restrict__ X, const int* __restrict__ start,
                      const int* __restrict__ lens, int Bn, int T,
                      float* __restrict__ out) {
    int idx = blockIdx.x * blockDim.x + threadIdx.x;
    int n1 = Bn * 2048;
    if (idx < n1) {
        int b = idx >> 11, e = idx & 2047;
        int last = start[b] + lens[b] - 1;
        out[(size_t)T * 2048 + idx] = X[(size_t)last * 2048 + e];
    } else if (idx < n1 + Bn * 1024) {
        int j = idx - n1;
        int b = j >> 10, e = j & 1023;
        int last = start[b] + lens[b] - 1;
        out[(size_t)T * 2048 + n1 + j] =
            __half2float(g_O1h[(size_t)last * 1024 + e]);
    }
}

// ---------------- launch ----------------------------------------------------
extern "C" void kernel_launch(void* const* d_in, const int* in_sizes, int n_in,
                              void* d_out, int out_size) {
    const float* X     = (const float*)d_in[0];
    const float* lf1   = (const float*)d_in[1];
    const float* lf2   = (const float*)d_in[2];
    const float* w1    = (const float*)d_in[3];
    const float* b1    = (const float*)d_in[4];
    const float* w2    = (const float*)d_in[5];
    const float* b2    = (const float*)d_in[6];
    const float* gamma = (const float*)d_in[7];
    const int* start   = (const int*)d_in[8];
    const int* lens    = (const int*)d_in[9];
    const int* maxlen  = (n_in > 10) ? (const int*)d_in[10] : nullptr;

    const int T  = in_sizes[0] / E_DIM;
    const int Bn = in_sizes[9];

    __half *pXh, *pW1h, *pW2h, *pO1h, *pC1h, *pC2h;
    cudaGetSymbolAddress((void**)&pXh, g_Xh);
    cudaGetSymbolAddress((void**)&pW1h, g_W1h);
    cudaGetSymbolAddress((void**)&pW2h, g_W2h);
    cudaGetSymbolAddress((void**)&pO1h, g_O1h);
    cudaGetSymbolAddress((void**)&pC1h, g_C1h);
    cudaGetSymbolAddress((void**)&pC2h, g_C2h);

    cudaFuncSetAttribute(gemm_f16,
                         cudaFuncAttributeMaxDynamicSharedMemorySize,
                         GEMM_SMEM);

    float* out = (float*)d_out;

    {
        int n8 = T * 2048 / 8;
        x_to_half<<<(n8 + 255) / 256, 256>>>(X, n8);
    }
    pack_weights<<<2048, 256>>>(w1, w2);
    {
        int nthr = Bn * 3072 * 32;
        init_vecs<<<(nthr + 255) / 256, 256>>>(w1, w2, b1, lf1, lf2, lens,
                                               maxlen, Bn);
    }
    // Layer 1: C1h[T,2048] = Xh[T,2048] @ W1h[2048,2048]^T
    gemm_f16<<<dim3(2048 / 128, T / 128), 256, GEMM_SMEM>>>(pXh, pW1h, pC1h,
                                                            T, 2048, 2048);
    combine1<<<(T * 128 + 255) / 256, 256>>>(b1, start, Bn, T);
    // Layer 2: C2h[T,4096] = O1h[T,1024] @ W2h[4096,1024]^T
    gemm_f16<<<dim3(4096 / 128, T / 128), 256, GEMM_SMEM>>>(pO1h, pW2h, pC2h,
                                                            T, 4096, 1024);
    combine2_norm<<<T, 256>>>(b2, gamma, start, Bn, out);
    tails<<<(Bn * 3072 + 255) / 256, 256>>>(X, start, lens, Bn, T, out);
    (void)out_size;
}

// round 15
// speedup vs baseline: 1.0455x; 1.0455x over previous
#include <cuda_runtime.h>
#include <cuda_fp16.h>
#include <cstdint>
#include <cstddef>

// Problem constants (fixed dataset: B=8 seqs, E=2048, T=24576, max_len=4096)
#define E_DIM 2048
#define T_MAX 24576
#define B_MAX 8
#define EPS_RMS 1e-6f

#define STAGES 3
#define BK 64
#define ST_H 72                          // 64 + 8 halves; 144B stride -> LDSM conflict-free
#define TILE_H (128 * ST_H)              // halves per (A or B) stage
#define STG_BYTES (2 * TILE_H * 2)       // A+B stage bytes (36864)
#define GEMM_SMEM (STAGES * STG_BYTES)   // 110592 bytes

// ---------------- scratch (device globals; allocation-free contract) -------
__device__ __align__(16) __half g_Xh[T_MAX * 2048];    // fp16 inputs
__device__ __align__(16) __half g_W1h[2048 * 2048];    // packed L1 weights [n][k]
__device__ __align__(16) __half g_W2h[4096 * 1024];    // packed L2 weights [n][k]
__device__ __align__(16) __half g_O1h[T_MAX * 1024];   // o1 per token (fp16)
__device__ __align__(16) __half g_C1h[T_MAX * 2048];   // L1 both taps (fp16)
__device__ __align__(16) __half g_C2h[T_MAX * 4096];   // L2 both taps (fp16)
__device__ float g_p0[B_MAX * 1024];   // W1_tap0 . x_prev(first token) per seq
__device__ float g_q0[B_MAX * 2048];   // W2_tap0 . o1_prev(first token) per seq

__device__ __forceinline__ uint32_t smem_u32(const void* p) {
    return (uint32_t)__cvta_generic_to_shared(p);
}

// ---------------- fused prep: X->fp16 | pack weights | boundary vectors ----
// Flat thread index split into three warp-aligned segments.
__global__ void prep(const float* __restrict__ X,
                     const float* __restrict__ w1,
                     const float* __restrict__ w2,
                     const float* __restrict__ b1,
                     const float* __restrict__ lf1,
                     const float* __restrict__ lf2,
                     const int* __restrict__ lens,
                     const int* __restrict__ maxlen_p, int Bn, int T) {
    const int n_a = T * 256;                 // uint4 stores of Xh (8 halves each)
    const int n_b = 2048 * 2048 + 4096 * 1024;  // weight elements
    int idx = blockIdx.x * blockDim.x + threadIdx.x;

    if (idx < n_a) {
        const float4* xp = (const float4*)(X) + (size_t)idx * 2;
        float4 a = xp[0], b = xp[1];
        __half2 h0 = __floats2half2_rn(a.x, a.y);
        __half2 h1 = __floats2half2_rn(a.z, a.w);
        __half2 h2 = __floats2half2_rn(b.x, b.y);
        __half2 h3 = __floats2half2_rn(b.z, b.w);
        uint4 v = make_uint4(*(uint32_t*)&h0, *(uint32_t*)&h1,
                             *(uint32_t*)&h2, *(uint32_t*)&h3);
        *((uint4*)g_Xh + idx) = v;
        return;
    }
    idx -= n_a;
    if (idx < n_b) {
        const int total1 = 2048 * 2048;
        if (idx < total1) {
            int n = idx >> 11, k = idx & 2047;
            float v = (n < 1024) ? w1[n * 4096 + k * 2 + 1]
                                 : w1[(n - 1024) * 4096 + k * 2];
            g_W1h[idx] = __float2half_rn(v);
        } else {
            int j = idx - total1;
            int n = j >> 10, k = j & 1023;
            float v = (n < 2048) ? w2[n * 2048 + k * 2 + 1]
                                 : w2[(n - 2048) * 2048 + k * 2];
            g_W2h[j] = __float2half_rn(v);
        }
        return;
    }
    idx -= n_b;
    // init_vecs: one warp per output, Bn*3072 warps
    {
        int gw = idx >> 5;
        int lane = idx & 31;
        int ml = maxlen_p ? *maxlen_p : 4096;
        int n_p0 = Bn * 1024;
        float s = 0.f;
        if (gw < n_p0) {
            int b = gw >> 10, o = gw & 1023;
            if (lens[b] == ml) {
                const float* wr = w1 + (size_t)o * 4096;
                const float* xr = lf1 + b * 2048;
                for (int i = lane; i < 2048; i += 32) s += wr[i * 2] * xr[i];
            }
#pragma unroll
            for (int off = 16; off; off >>= 1)
                s += __shfl_xor_sync(0xffffffffu, s, off);
            if (lane == 0) g_p0[gw] = s;
        } else if (gw < n_p0 + Bn * 2048) {
            int j = gw - n_p0;
            int b = j >> 11, o = j & 2047;
            bool full = (lens[b] == ml);
            const float* wr = w2 + (size_t)o * 2048;
            const float* vr = full ? (lf2 + b * 1024) : b1;
            for (int i = lane; i < 1024; i += 32) s += wr[i * 2] * vr[i];
#pragma unroll
            for (int off = 16; off; off >>= 1)
                s += __shfl_xor_sync(0xffffffffu, s, off);
            if (lane == 0) g_q0[j] = s;
        }
    }
}

// ---------------- fp16 tensor-core GEMM: C[M,N] = A[M,K] @ Bt[N,K]^T -------
// 128x128x64 block tile, 256 threads = 2x4 warps (warp tile 64x32),
// mma.sync.m16n8k16, ldmatrix, 3-stage cp.async, fp16 C output.
// R12 loop shape (measured optimum): next-stage loads after kk=0 MMAs.
__global__ __launch_bounds__(256, 2)
void gemm_f16(const __half* __restrict__ A, const __half* __restrict__ Bt,
              __half* __restrict__ C, int M, int N, int K) {
    extern __shared__ __half smem[];
    const uint32_t sb = smem_u32(smem);

    const int tid = threadIdx.x;
    const int warp = tid >> 5, lane = tid & 31;
    const int gid = lane >> 2, tid4 = lane & 3;
    const int wm = (warp >> 2) * 64;      // warp row offset in tile
    const int wn = (warp & 3) * 32;       // warp col offset in tile
    const int row0 = blockIdx.y * 128;
    const int col0 = blockIdx.x * 128;
    const int ktiles = K / BK;

    // per-lane ldmatrix byte offsets within a stage
    uint32_t aoff[4], boff[2];
#pragma unroll
    for (int mi = 0; mi < 4; mi++)
        aoff[mi] = ((wm + mi * 16 + (lane & 15)) * ST_H + (lane >> 4) * 8) * 2;
#pragma unroll
    for (int nj2 = 0; nj2 < 2; nj2++)
        boff[nj2] = ((wn + nj2 * 16 + ((lane >> 4) & 1) * 8 + (lane & 7)) * ST_H +
                     ((lane >> 3) & 1) * 8) * 2;

    float acc[4][4][4];
#pragma unroll
    for (int i = 0; i < 4; i++)
#pragma unroll
        for (int j = 0; j < 4; j++)
#pragma unroll
            for (int r = 0; r < 4; r++) acc[i][j][r] = 0.f;

    const __half* Abase = A + (size_t)row0 * K;
    const __half* Bbase = Bt + (size_t)col0 * K;

#define LOAD_STAGE(st, kt)                                                     \
    do {                                                                       \
        uint32_t ad = sb + (st) * STG_BYTES;                                   \
        uint32_t bd = ad + TILE_H * 2;                                         \
        _Pragma("unroll") for (int q = 0; q < 4; q++) {                        \
            int idx = tid + q * 256;                                           \
            int r = idx >> 3, c8 = (idx & 7) * 8;                              \
            asm volatile("cp.async.cg.shared.global [%0], [%1], 16;" ::        \
                             "r"(ad + (r * ST_H + c8) * 2),                    \
                             "l"(Abase + (size_t)r * K + (kt) * BK + c8));     \
        }                                                                      \
        _Pragma("unroll") for (int q = 0; q < 4; q++) {                        \
            int idx = tid + q * 256;                                           \
            int r = idx >> 3, c8 = (idx & 7) * 8;                              \
            asm volatile("cp.async.cg.shared.global [%0], [%1], 16;" ::        \
                             "r"(bd + (r * ST_H + c8) * 2),                    \
                             "l"(Bbase + (size_t)r * K + (kt) * BK + c8));     \
        }                                                                      \
    } while (0)

#define DO_KK(kk)                                                              \
    do {                                                                       \
        uint32_t af[4][4];                                                     \
        uint32_t bf[2][4];                                                     \
        _Pragma("unroll") for (int mi = 0; mi < 4; mi++)                       \
            asm volatile(                                                      \
                "ldmatrix.sync.aligned.m8n8.x4.shared.b16 {%0,%1,%2,%3}, [%4];"\
                : "=r"(af[mi][0]), "=r"(af[mi][1]), "=r"(af[mi][2]),           \
                  "=r"(af[mi][3])                                              \
                : "r"(as + aoff[mi] + (kk) * 32));                             \
        _Pragma("unroll") for (int nj2 = 0; nj2 < 2; nj2++)                    \
            asm volatile(                                                      \
                "ldmatrix.sync.aligned.m8n8.x4.shared.b16 {%0,%1,%2,%3}, [%4];"\
                : "=r"(bf[nj2][0]), "=r"(bf[nj2][1]), "=r"(bf[nj2][2]),        \
                  "=r"(bf[nj2][3])                                             \
                : "r"(bs + boff[nj2] + (kk) * 32));                            \
        _Pragma("unroll") for (int mi = 0; mi < 4; mi++)                       \
            _Pragma("unroll") for (int nj = 0; nj < 4; nj++) {                 \
                const uint32_t b0 = bf[nj >> 1][(nj & 1) * 2];                 \
                const uint32_t b1 = bf[nj >> 1][(nj & 1) * 2 + 1];             \
                asm volatile(                                                  \
                    "mma.sync.aligned.m16n8k16.row.col.f32.f16.f16.f32 "       \
                    "{%0,%1,%2,%3}, {%4,%5,%6,%7}, {%8,%9}, {%0,%1,%2,%3};"    \
                    : "+f"(acc[mi][nj][0]), "+f"(acc[mi][nj][1]),              \
                      "+f"(acc[mi][nj][2]), "+f"(acc[mi][nj][3])               \
                    : "r"(af[mi][0]), "r"(af[mi][1]), "r"(af[mi][2]),          \
                      "r"(af[mi][3]), "r"(b0), "r"(b1));                       \
            }                                                                  \
    } while (0)

    // prime pipeline: 2 stages
#pragma unroll
    for (int s = 0; s < STAGES - 1; s++) {
        if (s < ktiles) LOAD_STAGE(s, s);
        asm volatile("cp.async.commit_group;");
    }

    int st_cur = 0;                       // kt % 3, tracked incrementally
    int st_nxt = STAGES - 1;              // (kt + STAGES - 1) % 3
    for (int kt = 0; kt < ktiles; kt++) {
        asm volatile("cp.async.wait_group %0;" ::"n"(STAGES - 2));
        __syncthreads();

        uint32_t as = sb + st_cur * STG_BYTES;
        uint32_t bs = as + TILE_H * 2;
        if (++st_cur == STAGES) st_cur = 0;

        DO_KK(0);

        if (kt + STAGES - 1 < ktiles) LOAD_STAGE(st_nxt, kt + STAGES - 1);
        asm volatile("cp.async.commit_group;");
        if (++st_nxt == STAGES) st_nxt = 0;

        DO_KK(1);
        DO_KK(2);
        DO_KK(3);
    }

    // epilogue (fp16 output)
#pragma unroll
    for (int mi = 0; mi < 4; mi++) {
        int r0 = row0 + wm + mi * 16 + gid;
#pragma unroll
        for (int nj = 0; nj < 4; nj++) {
            int c = col0 + wn + nj * 8 + tid4 * 2;
            __half2 h0 = __floats2half2_rn(acc[mi][nj][0], acc[mi][nj][1]);
            __half2 h1 = __floats2half2_rn(acc[mi][nj][2], acc[mi][nj][3]);
            *(__half2*)&C[(size_t)r0 * N + c] = h0;
            *(__half2*)&C[(size_t)(r0 + 8) * N + c] = h1;
        }
    }
#undef LOAD_STAGE
#undef DO_KK
}

// ---- combine 1: o1 = C1h[t-1,1024+o]|p0 + C1h[t,o] + b1 -> fp16 O1h -------
__global__ void combine1(const float* __restrict__ b1,
                         const int* __restrict__ start, int Bn, int T) {
    int idx = blockIdx.x * blockDim.x + threadIdx.x;
    if (idx >= T * 128) return;
    int t = idx >> 7;
    int o = (idx & 127) << 3;
    int b = 0;
#pragma unroll
    for (int i = 1; i < 8; i++)
        if (i < Bn && t >= start[i]) b = i;

    uint4 curh = *(const uint4*)&g_C1h[(size_t)t * 2048 + o];
    float pv[8];
    if (t > start[b]) {
        uint4 ph = *(const uint4*)&g_C1h[(size_t)(t - 1) * 2048 + 1024 + o];
        const __half2* p2 = (const __half2*)&ph;
#pragma unroll
        for (int i = 0; i < 4; i++) {
            float2 f = __half22float2(p2[i]);
            pv[i * 2] = f.x; pv[i * 2 + 1] = f.y;
        }
    } else {
        float4 p0a = *(const float4*)&g_p0[b * 1024 + o];
        float4 p0b = *(const float4*)&g_p0[b * 1024 + o + 4];
        pv[0] = p0a.x; pv[1] = p0a.y; pv[2] = p0a.z; pv[3] = p0a.w;
        pv[4] = p0b.x; pv[5] = p0b.y; pv[6] = p0b.z; pv[7] = p0b.w;
    }
    float4 bba = *(const float4*)&b1[o];
    float4 bbb = *(const float4*)&b1[o + 4];
    float bv[8] = {bba.x, bba.y, bba.z, bba.w, bbb.x, bbb.y, bbb.z, bbb.w};

    const __half2* c2 = (const __half2*)&curh;
    __half2 r[4];
#pragma unroll
    for (int i = 0; i < 4; i++) {
        float2 f = __half22float2(c2[i]);
        r[i] = __floats2half2_rn(f.x + pv[i * 2] + bv[i * 2],
                                 f.y + pv[i * 2 + 1] + bv[i * 2 + 1]);
    }
    *(uint4*)&g_O1h[(size_t)t * 1024 + o] = *(uint4*)r;
}

// ---------------- combine 2 + RMSNorm: one block per token -----------------
// Residual read from fp16 Xh (measured numerically neutral).
__global__ __launch_bounds__(256)
void combine2_norm(const float* __restrict__ b2,
                   const float* __restrict__ gamma,
                   const int* __restrict__ start, int Bn,
                   float* __restrict__ out) {
    int t = blockIdx.x;
    int tid = threadIdx.x;
    int b = 0;
#pragma unroll
    for (int i = 1; i < 8; i++)
        if (i < Bn && t >= start[i]) b = i;
    bool first = (t == start[b]);
    int o = tid * 8;

    uint4 curh = *(const uint4*)&g_C2h[(size_t)t * 4096 + o];
    float pv[8];
    if (!first) {
        uint4 ph = *(const uint4*)&g_C2h[(size_t)(t - 1) * 4096 + 2048 + o];
        const __half2* p2 = (const __half2*)&ph;
#pragma unroll
        for (int i = 0; i < 4; i++) {
            float2 f = __half22float2(p2[i]);
            pv[i * 2] = f.x; pv[i * 2 + 1] = f.y;
        }
    } else {
        float4 qa = *(const float4*)&g_q0[b * 2048 + o];
        float4 qb = *(const float4*)&g_q0[b * 2048 + o + 4];
        pv[0] = qa.x; pv[1] = qa.y; pv[2] = qa.z; pv[3] = qa.w;
        pv[4] = qb.x; pv[5] = qb.y; pv[6] = qb.z; pv[7] = qb.w;
    }
    uint4 xh = *(const uint4*)&g_Xh[(size_t)t * 2048 + o];
    const __half2* x2 = (const __half2*)&xh;
    float xv[8];
#pragma unroll
    for (int i = 0; i < 4; i++) {
        float2 f = __half22float2(x2[i]);
        xv[i * 2] = f.x; xv[i * 2 + 1] = f.y;
    }
    float4 ba = *(const float4*)&b2[o];
    float4 bb = *(const float4*)&b2[o + 4];
    float bv[8] = {ba.x, ba.y, ba.z, ba.w, bb.x, bb.y, bb.z, bb.w};

    const __half2* c2 = (const __half2*)&curh;
    float vals[8];
    float sumsq = 0.f;
#pragma unroll
    for (int i = 0; i < 4; i++) {
        float2 f = __half22float2(c2[i]);
        float v0 = f.x + pv[i * 2] + xv[i * 2] + bv[i * 2];
        float v1 = f.y + pv[i * 2 + 1] + xv[i * 2 + 1] + bv[i * 2 + 1];
        vals[i * 2] = v0; vals[i * 2 + 1] = v1;
        sumsq += v0 * v0 + v1 * v1;
    }

#pragma unroll
    for (int off = 16; off; off >>= 1)
        sumsq += __shfl_xor_sync(0xffffffffu, sumsq, off);
    __shared__ float red[8];
    __shared__ float s_rs;
    if ((tid & 31) == 0) red[tid >> 5] = sumsq;
    __syncthreads();
    if (tid == 0) {
        float s = 0.f;
#pragma unroll
        for (int i = 0; i < 8; i++) s += red[i];
        s_rs = rsqrtf(s / (float)E_DIM + EPS_RMS);
    }
    __syncthreads();
    float r = s_rs;
    float4 ga = *(const float4*)&gamma[o];
    float4 gb = *(const float4*)&gamma[o + 4];
    float gv[8] = {ga.x, ga.y, ga.z, ga.w, gb.x, gb.y, gb.z, gb.w};
    float4 o0 = make_float4(vals[0] * r * gv[0], vals[1] * r * gv[1],
                            vals[2] * r * gv[2], vals[3] * r * gv[3]);
    float4 o1 = make_float4(vals[4] * r * gv[4], vals[5] * r * gv[5],
                            vals[6] * r * gv[6], vals[7] * r * gv[7]);
    *(float4*)&out[(size_t)t * 2048 + o] = o0;
    *(float4*)&out[(size_t)t * 2048 + o + 4] = o1;
}

// ---------------- cache outputs: lf1 = x[last] (exact fp32), lf2 = o1[last] -
__global__ void tails(const float* __restrict__ X, const int* __restrict__ start,
                      const int* __restrict__ lens, int Bn, int T,
                      float* __restrict__ out) {
    int idx = blockIdx.x * blockDim.x + threadIdx.x;
    int n1 = Bn * 2048;
    if (idx < n1) {
        int b = idx >> 11, e = idx & 2047;
        int last = start[b] + lens[b] - 1;
        out[(size_t)T * 2048 + idx] = X[(size_t)last * 2048 + e];
    } else if (idx < n1 + Bn * 1024) {
        int j = idx - n1;
        int b = j >> 10, e = j & 1023;
        int last = start[b] + lens[b] - 1;
        out[(size_t)T * 2048 + n1 + j] =
            __half2float(g_O1h[(size_t)last * 1024 + e]);
    }
}

// ---------------- launch ----------------------------------------------------
extern "C" void kernel_launch(void* const* d_in, const int* in_sizes, int n_in,
                              void* d_out, int out_size) {
    const float* X     = (const float*)d_in[0];
    const float* lf1   = (const float*)d_in[1];
    const float* lf2   = (const float*)d_in[2];
    const float* w1    = (const float*)d_in[3];
    const float* b1    = (const float*)d_in[4];
    const float* w2    = (const float*)d_in[5];
    const float* b2    = (const float*)d_in[6];
    const float* gamma = (const float*)d_in[7];
    const int* start   = (const int*)d_in[8];
    const int* lens    = (const int*)d_in[9];
    const int* maxlen  = (n_in > 10) ? (const int*)d_in[10] : nullptr;

    const int T  = in_sizes[0] / E_DIM;
    const int Bn = in_sizes[9];

    __half *pXh, *pW1h, *pW2h, *pO1h, *pC1h, *pC2h;
    cudaGetSymbolAddress((void**)&pXh, g_Xh);
    cudaGetSymbolAddress((void**)&pW1h, g_W1h);
    cudaGetSymbolAddress((void**)&pW2h, g_W2h);
    cudaGetSymbolAddress((void**)&pO1h, g_O1h);
    cudaGetSymbolAddress((void**)&pC1h, g_C1h);
    cudaGetSymbolAddress((void**)&pC2h, g_C2h);

    cudaFuncSetAttribute(gemm_f16,
                         cudaFuncAttributeMaxDynamicSharedMemorySize,
                         GEMM_SMEM);

    float* out = (float*)d_out;

    // fused prep: X->fp16 | weight pack | boundary vectors
    {
        int total = T * 256 + (2048 * 2048 + 4096 * 1024) + Bn * 3072 * 32;
        prep<<<(total + 255) / 256, 256>>>(X, w1, w2, b1, lf1, lf2, lens,
                                           maxlen, Bn, T);
    }
    // Layer 1: C1h[T,2048] = Xh[T,2048] @ W1h[2048,2048]^T
    gemm_f16<<<dim3(2048 / 128, T / 128), 256, GEMM_SMEM>>>(pXh, pW1h, pC1h,
                                                            T, 2048, 2048);
    combine1<<<(T * 128 + 255) / 256, 256>>>(b1, start, Bn, T);
    // Layer 2: C2h[T,4096] = O1h[T,1024] @ W2h[4096,1024]^T
    gemm_f16<<<dim3(4096 / 128, T / 128), 256, GEMM_SMEM>>>(pO1h, pW2h, pC2h,
                                                            T, 4096, 1024);
    combine2_norm<<<T, 256>>>(b2, gamma, start, Bn, out);
    tails<<<(Bn * 3072 + 255) / 256, 256>>>(X, start, lens, Bn, T, out);
    (void)out_size;
}

// round 16
// speedup vs baseline: 1.0871x; 1.0398x over previous
#include <cuda_runtime.h>
#include <cuda_fp16.h>
#include <cstdint>
#include <cstddef>

// Problem constants (fixed dataset: B=8 seqs, E=2048, T=24576, max_len=4096)
#define E_DIM 2048
#define T_MAX 24576
#define B_MAX 8
#define EPS_RMS 1e-6f

#define STAGES 3
#define BK 64
#define ST_H 72                          // 64 + 8 halves; 144B stride -> LDSM conflict-free
#define TILE_H (128 * ST_H)              // halves per (A or B) stage
#define STG_BYTES (2 * TILE_H * 2)       // A+B stage bytes (36864)
#define GEMM_SMEM (STAGES * STG_BYTES)   // 110592 bytes

// ---------------- scratch (device globals; allocation-free contract) -------
__device__ __align__(16) __half g_Xh[T_MAX * 2048];    // fp16 inputs
__device__ __align__(16) __half g_W1h[2048 * 2048];    // packed L1 weights [n][k]
__device__ __align__(16) __half g_W2h[2048 * 2048];    // packed L2 weights [n][k]: k<1024 tap1, k>=1024 tap0
__device__ __align__(16) __half g_A2[T_MAX * 2048];    // [o1[t] ; o1prev[t]] per token
__device__ __align__(16) __half g_C1h[T_MAX * 2048];   // L1 both taps (fp16)
__device__ __align__(16) __half g_C2h[T_MAX * 2048];   // L2 conv output (fp16)
__device__ float g_p0[B_MAX * 1024];   // W1_tap0 . x_prev(first token) per seq

__device__ __forceinline__ uint32_t smem_u32(const void* p) {
    return (uint32_t)__cvta_generic_to_shared(p);
}

// ---------------- fused prep: X->fp16 | pack weights | p0 vectors ----------
// Flat thread index split into three warp-aligned segments.
__global__ void prep(const float* __restrict__ X,
                     const float* __restrict__ w1,
                     const float* __restrict__ w2,
                     const float* __restrict__ lf1,
                     const int* __restrict__ lens,
                     const int* __restrict__ maxlen_p, int Bn, int T) {
    const int n_a = T * 256;                 // uint4 stores of Xh (8 halves each)
    const int n_b = 2048 * 2048 + 2048 * 2048;  // W1 + W2 elements
    int idx = blockIdx.x * blockDim.x + threadIdx.x;

    if (idx < n_a) {
        const float4* xp = (const float4*)(X) + (size_t)idx * 2;
        float4 a = xp[0], b = xp[1];
        __half2 h0 = __floats2half2_rn(a.x, a.y);
        __half2 h1 = __floats2half2_rn(a.z, a.w);
        __half2 h2 = __floats2half2_rn(b.x, b.y);
        __half2 h3 = __floats2half2_rn(b.z, b.w);
        uint4 v = make_uint4(*(uint32_t*)&h0, *(uint32_t*)&h1,
                             *(uint32_t*)&h2, *(uint32_t*)&h3);
        *((uint4*)g_Xh + idx) = v;
        return;
    }
    idx -= n_a;
    if (idx < n_b) {
        const int total1 = 2048 * 2048;
        if (idx < total1) {
            // W1h[n][k]: n<1024 -> w1[n,k,1] ; else w1[n-1024,k,0]
            int n = idx >> 11, k = idx & 2047;
            float v = (n < 1024) ? w1[n * 4096 + k * 2 + 1]
                                 : w1[(n - 1024) * 4096 + k * 2];
            g_W1h[idx] = __float2half_rn(v);
        } else {
            // W2h[n][k]: k<1024 -> w2[n,k,1] (tap1) ; k>=1024 -> w2[n,k-1024,0] (tap0)
            int j = idx - total1;
            int n = j >> 11, k = j & 2047;
            float v = (k < 1024) ? w2[n * 2048 + k * 2 + 1]
                                 : w2[n * 2048 + (k - 1024) * 2];
            g_W2h[j] = __float2half_rn(v);
        }
        return;
    }
    idx -= n_b;
    // p0: one warp per output, Bn*1024 warps
    {
        int gw = idx >> 5;
        int lane = idx & 31;
        int ml = maxlen_p ? *maxlen_p : 4096;
        if (gw < Bn * 1024) {
            int b = gw >> 10, o = gw & 1023;
            float s = 0.f;
            if (lens[b] == ml) {
                const float* wr = w1 + (size_t)o * 4096;
                const float* xr = lf1 + b * 2048;
                for (int i = lane; i < 2048; i += 32) s += wr[i * 2] * xr[i];
            }
#pragma unroll
            for (int off = 16; off; off >>= 1)
                s += __shfl_xor_sync(0xffffffffu, s, off);
            if (lane == 0) g_p0[gw] = s;
        }
    }
}

// ---------------- fp16 tensor-core GEMM: C[M,N] = A[M,K] @ Bt[N,K]^T -------
// 128x128x64 block tile, 256 threads = 2x4 warps (warp tile 64x32),
// mma.sync.m16n8k16, ldmatrix, 3-stage cp.async, fp16 C output.
// R12 loop shape (measured optimum): next-stage loads after kk=0 MMAs.
__global__ __launch_bounds__(256, 2)
void gemm_f16(const __half* __restrict__ A, const __half* __restrict__ Bt,
              __half* __restrict__ C, int M, int N, int K) {
    extern __shared__ __half smem[];
    const uint32_t sb = smem_u32(smem);

    const int tid = threadIdx.x;
    const int warp = tid >> 5, lane = tid & 31;
    const int gid = lane >> 2, tid4 = lane & 3;
    const int wm = (warp >> 2) * 64;      // warp row offset in tile
    const int wn = (warp & 3) * 32;       // warp col offset in tile
    const int row0 = blockIdx.y * 128;
    const int col0 = blockIdx.x * 128;
    const int ktiles = K / BK;

    // per-lane ldmatrix byte offsets within a stage
    uint32_t aoff[4], boff[2];
#pragma unroll
    for (int mi = 0; mi < 4; mi++)
        aoff[mi] = ((wm + mi * 16 + (lane & 15)) * ST_H + (lane >> 4) * 8) * 2;
#pragma unroll
    for (int nj2 = 0; nj2 < 2; nj2++)
        boff[nj2] = ((wn + nj2 * 16 + ((lane >> 4) & 1) * 8 + (lane & 7)) * ST_H +
                     ((lane >> 3) & 1) * 8) * 2;

    float acc[4][4][4];
#pragma unroll
    for (int i = 0; i < 4; i++)
#pragma unroll
        for (int j = 0; j < 4; j++)
#pragma unroll
            for (int r = 0; r < 4; r++) acc[i][j][r] = 0.f;

    const __half* Abase = A + (size_t)row0 * K;
    const __half* Bbase = Bt + (size_t)col0 * K;

#define LOAD_STAGE(st, kt)                                                     \
    do {                                                                       \
        uint32_t ad = sb + (st) * STG_BYTES;                                   \
        uint32_t bd = ad + TILE_H * 2;                                         \
        _Pragma("unroll") for (int q = 0; q < 4; q++) {                        \
            int idx = tid + q * 256;                                           \
            int r = idx >> 3, c8 = (idx & 7) * 8;                              \
            asm volatile("cp.async.cg.shared.global [%0], [%1], 16;" ::        \
                             "r"(ad + (r * ST_H + c8) * 2),                    \
                             "l"(Abase + (size_t)r * K + (kt) * BK + c8));     \
        }                                                                      \
        _Pragma("unroll") for (int q = 0; q < 4; q++) {                        \
            int idx = tid + q * 256;                                           \
            int r = idx >> 3, c8 = (idx & 7) * 8;                              \
            asm volatile("cp.async.cg.shared.global [%0], [%1], 16;" ::        \
                             "r"(bd + (r * ST_H + c8) * 2),                    \
                             "l"(Bbase + (size_t)r * K + (kt) * BK + c8));     \
        }                                                                      \
    } while (0)

#define DO_KK(kk)                                                              \
    do {                                                                       \
        uint32_t af[4][4];                                                     \
        uint32_t bf[2][4];                                                     \
        _Pragma("unroll") for (int mi = 0; mi < 4; mi++)                       \
            asm volatile(                                                      \
                "ldmatrix.sync.aligned.m8n8.x4.shared.b16 {%0,%1,%2,%3}, [%4];"\
                : "=r"(af[mi][0]), "=r"(af[mi][1]), "=r"(af[mi][2]),           \
                  "=r"(af[mi][3])                                              \
                : "r"(as + aoff[mi] + (kk) * 32));                             \
        _Pragma("unroll") for (int nj2 = 0; nj2 < 2; nj2++)                    \
            asm volatile(                                                      \
                "ldmatrix.sync.aligned.m8n8.x4.shared.b16 {%0,%1,%2,%3}, [%4];"\
                : "=r"(bf[nj2][0]), "=r"(bf[nj2][1]), "=r"(bf[nj2][2]),        \
                  "=r"(bf[nj2][3])                                             \
                : "r"(bs + boff[nj2] + (kk) * 32));                            \
        _Pragma("unroll") for (int mi = 0; mi < 4; mi++)                       \
            _Pragma("unroll") for (int nj = 0; nj < 4; nj++) {                 \
                const uint32_t b0 = bf[nj >> 1][(nj & 1) * 2];                 \
                const uint32_t b1 = bf[nj >> 1][(nj & 1) * 2 + 1];             \
                asm volatile(                                                  \
                    "mma.sync.aligned.m16n8k16.row.col.f32.f16.f16.f32 "       \
                    "{%0,%1,%2,%3}, {%4,%5,%6,%7}, {%8,%9}, {%0,%1,%2,%3};"    \
                    : "+f"(acc[mi][nj][0]), "+f"(acc[mi][nj][1]),              \
                      "+f"(acc[mi][nj][2]), "+f"(acc[mi][nj][3])               \
                    : "r"(af[mi][0]), "r"(af[mi][1]), "r"(af[mi][2]),          \
                      "r"(af[mi][3]), "r"(b0), "r"(b1));                       \
            }                                                                  \
    } while (0)

    // prime pipeline: 2 stages
#pragma unroll
    for (int s = 0; s < STAGES - 1; s++) {
        if (s < ktiles) LOAD_STAGE(s, s);
        asm volatile("cp.async.commit_group;");
    }

    int st_cur = 0;                       // kt % 3, tracked incrementally
    int st_nxt = STAGES - 1;              // (kt + STAGES - 1) % 3
    for (int kt = 0; kt < ktiles; kt++) {
        asm volatile("cp.async.wait_group %0;" ::"n"(STAGES - 2));
        __syncthreads();

        uint32_t as = sb + st_cur * STG_BYTES;
        uint32_t bs = as + TILE_H * 2;
        if (++st_cur == STAGES) st_cur = 0;

        DO_KK(0);

        if (kt + STAGES - 1 < ktiles) LOAD_STAGE(st_nxt, kt + STAGES - 1);
        asm volatile("cp.async.commit_group;");
        if (++st_nxt == STAGES) st_nxt = 0;

        DO_KK(1);
        DO_KK(2);
        DO_KK(3);
    }

    // epilogue (fp16 output)
#pragma unroll
    for (int mi = 0; mi < 4; mi++) {
        int r0 = row0 + wm + mi * 16 + gid;
#pragma unroll
        for (int nj = 0; nj < 4; nj++) {
            int c = col0 + wn + nj * 8 + tid4 * 2;
            __half2 h0 = __floats2half2_rn(acc[mi][nj][0], acc[mi][nj][1]);
            __half2 h1 = __floats2half2_rn(acc[mi][nj][2], acc[mi][nj][3]);
            *(__half2*)&C[(size_t)r0 * N + c] = h0;
            *(__half2*)&C[(size_t)(r0 + 8) * N + c] = h1;
        }
    }
#undef LOAD_STAGE
#undef DO_KK
}

// ---- combine 1: o1 = C1h[t-1,1024+o]|p0 + C1h[t,o] + b1 -> A2 rows --------
// Writes A2[t][o] = o1[t][o]; A2[t+1][1024+o] = o1[t][o] (unless t+1 is a
// sequence start or end); A2[t][1024+o] = (full? lf2 : b1) when t is a start.
__global__ void combine1(const float* __restrict__ b1,
                         const float* __restrict__ lf2,
                         const int* __restrict__ start,
                         const int* __restrict__ lens,
                         const int* __restrict__ maxlen_p, int Bn, int T) {
    int idx = blockIdx.x * blockDim.x + threadIdx.x;
    if (idx >= T * 128) return;
    int t = idx >> 7;
    int o = (idx & 127) << 3;
    int b = 0;
#pragma unroll
    for (int i = 1; i < 8; i++)
        if (i < Bn && t >= start[i]) b = i;

    uint4 curh = *(const uint4*)&g_C1h[(size_t)t * 2048 + o];
    float pv[8];
    if (t > start[b]) {
        uint4 ph = *(const uint4*)&g_C1h[(size_t)(t - 1) * 2048 + 1024 + o];
        const __half2* p2 = (const __half2*)&ph;
#pragma unroll
        for (int i = 0; i < 4; i++) {
            float2 f = __half22float2(p2[i]);
            pv[i * 2] = f.x; pv[i * 2 + 1] = f.y;
        }
    } else {
        float4 p0a = *(const float4*)&g_p0[b * 1024 + o];
        float4 p0b = *(const float4*)&g_p0[b * 1024 + o + 4];
        pv[0] = p0a.x; pv[1] = p0a.y; pv[2] = p0a.z; pv[3] = p0a.w;
        pv[4] = p0b.x; pv[5] = p0b.y; pv[6] = p0b.z; pv[7] = p0b.w;
    }
    float4 bba = *(const float4*)&b1[o];
    float4 bbb = *(const float4*)&b1[o + 4];
    float bv[8] = {bba.x, bba.y, bba.z, bba.w, bbb.x, bbb.y, bbb.z, bbb.w};

    const __half2* c2 = (const __half2*)&curh;
    __half2 r[4];
#pragma unroll
    for (int i = 0; i < 4; i++) {
        float2 f = __half22float2(c2[i]);
        r[i] = __floats2half2_rn(f.x + pv[i * 2] + bv[i * 2],
                                 f.y + pv[i * 2 + 1] + bv[i * 2 + 1]);
    }
    *(uint4*)&g_A2[(size_t)t * 2048 + o] = *(uint4*)r;

    // forward write: o1[t] is the prev of token t+1 (same sequence only)
    bool next_is_start = (b + 1 < Bn) && (t + 1 == start[b + 1]);
    if (t + 1 < T && !next_is_start)
        *(uint4*)&g_A2[(size_t)(t + 1) * 2048 + 1024 + o] = *(uint4*)r;

    // boundary prev for the first token of each sequence
    if (t == start[b]) {
        int ml = maxlen_p ? *maxlen_p : 4096;
        bool full = (lens[b] == ml);
        __half2 v[4];
        if (full) {
            float4 a = *(const float4*)&lf2[b * 1024 + o];
            float4 c = *(const float4*)&lf2[b * 1024 + o + 4];
            v[0] = __floats2half2_rn(a.x, a.y);
            v[1] = __floats2half2_rn(a.z, a.w);
            v[2] = __floats2half2_rn(c.x, c.y);
            v[3] = __floats2half2_rn(c.z, c.w);
        } else {
            v[0] = __floats2half2_rn(bv[0], bv[1]);
            v[1] = __floats2half2_rn(bv[2], bv[3]);
            v[2] = __floats2half2_rn(bv[4], bv[5]);
            v[3] = __floats2half2_rn(bv[6], bv[7]);
        }
        *(uint4*)&g_A2[(size_t)t * 2048 + 1024 + o] = *(uint4*)v;
    }
}

// ---------------- combine 2 + RMSNorm: one block per token -----------------
// out = gamma * rmsnorm(C2h + Xh + b2). No prev-row logic (folded into GEMM).
__global__ __launch_bounds__(256)
void combine2_norm(const float* __restrict__ b2,
                   const float* __restrict__ gamma,
                   float* __restrict__ out) {
    int t = blockIdx.x;
    int tid = threadIdx.x;
    int o = tid * 8;

    uint4 curh = *(const uint4*)&g_C2h[(size_t)t * 2048 + o];
    uint4 xh = *(const uint4*)&g_Xh[(size_t)t * 2048 + o];
    float4 ba = *(const float4*)&b2[o];
    float4 bb = *(const float4*)&b2[o + 4];
    float bv[8] = {ba.x, ba.y, ba.z, ba.w, bb.x, bb.y, bb.z, bb.w};

    const __half2* c2 = (const __half2*)&curh;
    const __half2* x2 = (const __half2*)&xh;
    float vals[8];
    float sumsq = 0.f;
#pragma unroll
    for (int i = 0; i < 4; i++) {
        float2 fc = __half22float2(c2[i]);
        float2 fx = __half22float2(x2[i]);
        float v0 = fc.x + fx.x + bv[i * 2];
        float v1 = fc.y + fx.y + bv[i * 2 + 1];
        vals[i * 2] = v0; vals[i * 2 + 1] = v1;
        sumsq += v0 * v0 + v1 * v1;
    }

#pragma unroll
    for (int off = 16; off; off >>= 1)
        sumsq += __shfl_xor_sync(0xffffffffu, sumsq, off);
    __shared__ float red[8];
    __shared__ float s_rs;
    if ((tid & 31) == 0) red[tid >> 5] = sumsq;
    __syncthreads();
    if (tid == 0) {
        float s = 0.f;
#pragma unroll
        for (int i = 0; i < 8; i++) s += red[i];
        s_rs = rsqrtf(s / (float)E_DIM + EPS_RMS);
    }
    __syncthreads();
    float r = s_rs;
    float4 ga = *(const float4*)&gamma[o];
    float4 gb = *(const float4*)&gamma[o + 4];
    float gv[8] = {ga.x, ga.y, ga.z, ga.w, gb.x, gb.y, gb.z, gb.w};
    float4 o0 = make_float4(vals[0] * r * gv[0], vals[1] * r * gv[1],
                            vals[2] * r * gv[2], vals[3] * r * gv[3]);
    float4 o1 = make_float4(vals[4] * r * gv[4], vals[5] * r * gv[5],
                            vals[6] * r * gv[6], vals[7] * r * gv[7]);
    *(float4*)&out[(size_t)t * 2048 + o] = o0;
    *(float4*)&out[(size_t)t * 2048 + o + 4] = o1;
}

// ---------------- cache outputs: lf1 = x[last] (exact fp32), lf2 = o1[last] -
__global__ void tails(const float* __restrict__ X, const int* __restrict__ start,
                      const int* __restrict__ lens, int Bn, int T,
                      float* __restrict__ out) {
    int idx = blockIdx.x * blockDim.x + threadIdx.x;
    int n1 = Bn * 2048;
    if (idx < n1) {
        int b = idx >> 11, e = idx & 2047;
        int last = start[b] + lens[b] - 1;
        out[(size_t)T * 2048 + idx] = X[(size_t)last * 2048 + e];
    } else if (idx < n1 + Bn * 1024) {
        int j = idx - n1;
        int b = j >> 10, e = j & 1023;
        int last = start[b] + lens[b] - 1;
        out[(size_t)T * 2048 + n1 + j] =
            __half2float(g_A2[(size_t)last * 2048 + e]);
    }
}

// ---------------- launch ----------------------------------------------------
extern "C" void kernel_launch(void* const* d_in, const int* in_sizes, int n_in,
                              void* d_out, int out_size) {
    const float* X     = (const float*)d_in[0];
    const float* lf1   = (const float*)d_in[1];
    const float* lf2   = (const float*)d_in[2];
    const float* w1    = (const float*)d_in[3];
    const float* b1    = (const float*)d_in[4];
    const float* w2    = (const float*)d_in[5];
    const float* b2    = (const float*)d_in[6];
    const float* gamma = (const float*)d_in[7];
    const int* start   = (const int*)d_in[8];
    const int* lens    = (const int*)d_in[9];
    const int* maxlen  = (n_in > 10) ? (const int*)d_in[10] : nullptr;

    const int T  = in_sizes[0] / E_DIM;
    const int Bn = in_sizes[9];

    __half *pXh, *pW1h, *pW2h, *pA2, *pC1h, *pC2h;
    cudaGetSymbolAddress((void**)&pXh, g_Xh);
    cudaGetSymbolAddress((void**)&pW1h, g_W1h);
    cudaGetSymbolAddress((void**)&pW2h, g_W2h);
    cudaGetSymbolAddress((void**)&pA2, g_A2);
    cudaGetSymbolAddress((void**)&pC1h, g_C1h);
    cudaGetSymbolAddress((void**)&pC2h, g_C2h);

    cudaFuncSetAttribute(gemm_f16,
                         cudaFuncAttributeMaxDynamicSharedMemorySize,
                         GEMM_SMEM);

    float* out = (float*)d_out;

    // fused prep: X->fp16 | weight pack | p0 vectors
    {
        int total = T * 256 + 2 * 2048 * 2048 + Bn * 1024 * 32;
        prep<<<(total + 255) / 256, 256>>>(X, w1, w2, lf1, lens, maxlen, Bn, T);
    }
    // Layer 1: C1h[T,2048] = Xh[T,2048] @ W1h[2048,2048]^T
    gemm_f16<<<dim3(2048 / 128, T / 128), 256, GEMM_SMEM>>>(pXh, pW1h, pC1h,
                                                            T, 2048, 2048);
    combine1<<<(T * 128 + 255) / 256, 256>>>(b1, lf2, start, lens, maxlen,
                                             Bn, T);
    // Layer 2: C2h[T,2048] = A2[T,2048] @ W2h[2048,2048]^T (taps folded into K)
    gemm_f16<<<dim3(2048 / 128, T / 128), 256, GEMM_SMEM>>>(pA2, pW2h, pC2h,
                                                            T, 2048, 2048);
    combine2_norm<<<T, 256>>>(b2, gamma, out);
    tails<<<(Bn * 3072 + 255) / 256, 256>>>(X, start, lens, Bn, T, out);
    (void)out_size;
}